// round 16
// baseline (speedup 1.0000x reference)
#include <cuda_runtime.h>
#include <cuda_fp16.h>
#include <cstdint>

#define NN 16384
#define NH 128
#define NE (NN*32)
#define CAP 96     // bucket capacity: in-degree is Binom(524288,1/16384), 96 = 11 sigma

// ---------------- device scratch ----------------
__device__ int g_cnt[NN];                      // edges landed per target
__device__ __align__(16) float g_h[NN*NH];     // x @ W (fp32)
__device__ __align__(16) __half g_hh[NN*NH];   // fp16 copy of h (gather source)
__device__ __align__(16) __half g_h2[NN*NH];   // relu(gcn) in fp16
__device__ int g_csr[NN*CAP];                  // bucketed edge sources

#define KC 64
#define LDSW 68    // k_xw smem stride (floats)
#define KCH 32     // gemm k-chunk (halves)
#define LDSH 40    // gemm smem stride in halves: 80B rows (16B-aligned);
                   // frag word = (20*grp + qc)%32 bijective -> conflict-free
#define TS 132     // transposed staging stride (floats)

__device__ __forceinline__ float tf32r(float v){
    uint32_t t; asm("cvt.rna.tf32.f32 %0, %1;" : "=r"(t) : "f"(v));
    return __uint_as_float(t);
}
__device__ __forceinline__ void cp16(void* dst, const void* src){
    uint32_t d = (uint32_t)__cvta_generic_to_shared(dst);
    asm volatile("cp.async.cg.shared.global [%0], [%1], 16;" :: "r"(d), "l"(src));
}
__device__ __forceinline__ void mma_tf32(float* d,
        uint32_t a0, uint32_t a1, uint32_t a2, uint32_t a3,
        uint32_t b0, uint32_t b1){
    asm volatile(
        "mma.sync.aligned.m16n8k8.row.col.f32.tf32.tf32.f32 "
        "{%0,%1,%2,%3}, {%4,%5,%6,%7}, {%8,%9}, {%0,%1,%2,%3};"
        : "+f"(d[0]), "+f"(d[1]), "+f"(d[2]), "+f"(d[3])
        : "r"(a0), "r"(a1), "r"(a2), "r"(a3), "r"(b0), "r"(b1));
}
__device__ __forceinline__ void mma_f16(float* d,
        uint32_t a0, uint32_t a1, uint32_t a2, uint32_t a3,
        uint32_t b0, uint32_t b1){
    asm volatile(
        "mma.sync.aligned.m16n8k16.row.col.f32.f16.f16.f32 "
        "{%0,%1,%2,%3}, {%4,%5,%6,%7}, {%8,%9}, {%0,%1,%2,%3};"
        : "+f"(d[0]), "+f"(d[1]), "+f"(d[2]), "+f"(d[3])
        : "r"(a0), "r"(a1), "r"(a2), "r"(a3), "r"(b0), "r"(b1));
}

// ---------------- stage 1: zero bucket counters ----------------
__global__ void k_init(){
    int i = blockIdx.x * blockDim.x + threadIdx.x;
    if (i < NN) g_cnt[i] = 0;
}

// ---------------- stage 2: bucket fill, 4 edges/thread (int4) ---------------
__global__ void k_fill(const int* __restrict__ ei){
    int i = blockIdx.x * blockDim.x + threadIdx.x;
    if (i >= NE/4) return;
    int4 r = reinterpret_cast<const int4*>(ei)[i];
    int4 c = reinterpret_cast<const int4*>(ei + NE)[i];
    g_csr[c.x*CAP + atomicAdd(&g_cnt[c.x], 1)] = r.x;
    g_csr[c.y*CAP + atomicAdd(&g_cnt[c.y], 1)] = r.y;
    g_csr[c.z*CAP + atomicAdd(&g_cnt[c.z], 1)] = r.z;
    g_csr[c.w*CAP + atomicAdd(&g_cnt[c.w], 1)] = r.w;
}

// ---------------- stage 3: h = x @ W via tf32 mma (emits fp32 + fp16) -------
__global__ void __launch_bounds__(256, 2) k_xw(const float* __restrict__ x,
                                               const float* __restrict__ W){
    extern __shared__ float sm[];
    float* As = sm;
    float* Bs = sm + 128*LDSW;

    int tid  = threadIdx.x;
    int lane = tid & 31;
    int wid  = tid >> 5;
    int m0w  = (wid >> 2) * 64;
    int n0w  = (wid & 3) * 32;
    int row0 = blockIdx.x * 128;
    int grp  = lane >> 2, qc = lane & 3;

    float acc[4][4][4];
#pragma unroll
    for (int i = 0; i < 4; i++)
#pragma unroll
        for (int j = 0; j < 4; j++)
#pragma unroll
            for (int q = 0; q < 4; q++) acc[i][j][q] = 0.0f;

    for (int kc = 0; kc < 2; ++kc){
        if (kc) __syncthreads();
#pragma unroll
        for (int i = 0; i < 8; ++i){
            int idx = i*256 + tid;
            int r = idx >> 4, c4 = idx & 15;
            float4 v = *reinterpret_cast<const float4*>(x + (size_t)(row0 + r)*NH + kc*KC + c4*4);
            v.x = tf32r(v.x); v.y = tf32r(v.y); v.z = tf32r(v.z); v.w = tf32r(v.w);
            *reinterpret_cast<float4*>(As + r*LDSW + c4*4) = v;
        }
#pragma unroll
        for (int i = 0; i < 8; ++i){
            int idx = i*256 + tid;
            int n = idx & 127, kk4 = idx >> 7;
            float4 v;
            v.x = tf32r(W[(size_t)(kc*KC + kk4*4 + 0)*NH + n]);
            v.y = tf32r(W[(size_t)(kc*KC + kk4*4 + 1)*NH + n]);
            v.z = tf32r(W[(size_t)(kc*KC + kk4*4 + 2)*NH + n]);
            v.w = tf32r(W[(size_t)(kc*KC + kk4*4 + 3)*NH + n]);
            *reinterpret_cast<float4*>(Bs + n*LDSW + kk4*4) = v;
        }
        __syncthreads();

#pragma unroll
        for (int k8 = 0; k8 < KC/8; ++k8){
            int kb = k8*8;
            uint32_t a[4][4], b[4][2];
#pragma unroll
            for (int mf = 0; mf < 4; ++mf){
                int r0 = m0w + mf*16 + grp;
                a[mf][0] = __float_as_uint(As[r0*LDSW     + kb + qc]);
                a[mf][1] = __float_as_uint(As[(r0+8)*LDSW + kb + qc]);
                a[mf][2] = __float_as_uint(As[r0*LDSW     + kb + qc + 4]);
                a[mf][3] = __float_as_uint(As[(r0+8)*LDSW + kb + qc + 4]);
            }
#pragma unroll
            for (int nf = 0; nf < 4; ++nf){
                int rn = n0w + nf*8 + grp;
                b[nf][0] = __float_as_uint(Bs[rn*LDSW + kb + qc]);
                b[nf][1] = __float_as_uint(Bs[rn*LDSW + kb + qc + 4]);
            }
#pragma unroll
            for (int mf = 0; mf < 4; ++mf)
#pragma unroll
                for (int nf = 0; nf < 4; ++nf)
                    mma_tf32(acc[mf][nf], a[mf][0], a[mf][1], a[mf][2], a[mf][3],
                             b[nf][0], b[nf][1]);
        }
    }

#pragma unroll
    for (int mf = 0; mf < 4; ++mf)
#pragma unroll
        for (int nf = 0; nf < 4; ++nf){
            int r = m0w + mf*16 + grp;
            int c = n0w + nf*8 + 2*qc;
            *reinterpret_cast<float2*>(g_h + (size_t)(row0 + r)*NH + c) =
                make_float2(acc[mf][nf][0], acc[mf][nf][1]);
            *reinterpret_cast<float2*>(g_h + (size_t)(row0 + r + 8)*NH + c) =
                make_float2(acc[mf][nf][2], acc[mf][nf][3]);
            reinterpret_cast<__half2*>(g_hh + (size_t)(row0 + r)*NH)[c>>1] =
                __floats2half2_rn(acc[mf][nf][0], acc[mf][nf][1]);
            reinterpret_cast<__half2*>(g_hh + (size_t)(row0 + r + 8)*NH)[c>>1] =
                __floats2half2_rn(acc[mf][nf][2], acc[mf][nf][3]);
        }
}

// ---------------- stage 4: fused gather, split-warp (2 edges / iter) --------
// half-warp 0 -> even edges, half-warp 1 -> odd edges; lane owns 8 columns
// (16B of the fp16 row). Combine halves via shfl_xor(16) at the end.
__global__ void k_gather(const float* __restrict__ bias){
    int warp = (blockIdx.x * blockDim.x + threadIdx.x) >> 5;
    if (warp >= NN) return;
    int lane  = threadIdx.x & 31;
    int half  = lane >> 4;       // 0 or 1
    int col16 = lane & 15;       // owns halves [col16*8, col16*8+8)
    int cn = warp;

    int   cntc = g_cnt[cn];
    float degc = (float)(cntc + 1);          // + self-loop
    float dic  = rsqrtf(degc);
    int beg = cn*CAP, end = cn*CAP + cntc;

    float acc[8];
    if (half == 0){
        float inv = 1.0f / degc;
        const float4* hp = reinterpret_cast<const float4*>(g_h + (size_t)cn*NH + col16*8);
        const float4* bp = reinterpret_cast<const float4*>(bias + col16*8);
        float4 h0 = hp[0], h1 = hp[1];
        float4 b0 = bp[0], b1 = bp[1];
        acc[0]=h0.x*inv+b0.x; acc[1]=h0.y*inv+b0.y; acc[2]=h0.z*inv+b0.z; acc[3]=h0.w*inv+b0.w;
        acc[4]=h1.x*inv+b1.x; acc[5]=h1.y*inv+b1.y; acc[6]=h1.z*inv+b1.z; acc[7]=h1.w*inv+b1.w;
    } else {
#pragma unroll
        for (int i = 0; i < 8; ++i) acc[i] = 0.0f;
    }

    for (int j = beg; j < end; j += 32){
        int me = j + lane;
        int src = 0; float wsrc = 0.0f;
        if (me < end){
            src  = g_csr[me];
            wsrc = dic * rsqrtf((float)(g_cnt[src] + 1));
        }
        int cb = min(32, end - j);
        int kmax = (cb + 1) >> 1;

#define GATH_STEP(kk) do {                                                     \
            int e = 2*(kk) + half;                                             \
            int   r = __shfl_sync(0xffffffffu, src,  e);                       \
            float w = __shfl_sync(0xffffffffu, wsrc, e);                       \
            uint4 hv = reinterpret_cast<const uint4*>(g_hh + (size_t)r*NH)[col16]; \
            float2 f0 = __half22float2(*reinterpret_cast<__half2*>(&hv.x));    \
            float2 f1 = __half22float2(*reinterpret_cast<__half2*>(&hv.y));    \
            float2 f2 = __half22float2(*reinterpret_cast<__half2*>(&hv.z));    \
            float2 f3 = __half22float2(*reinterpret_cast<__half2*>(&hv.w));    \
            acc[0]+=w*f0.x; acc[1]+=w*f0.y; acc[2]+=w*f1.x; acc[3]+=w*f1.y;    \
            acc[4]+=w*f2.x; acc[5]+=w*f2.y; acc[6]+=w*f3.x; acc[7]+=w*f3.y;    \
        } while(0)

        if (kmax == 16){
#pragma unroll
            for (int kk = 0; kk < 16; ++kk) GATH_STEP(kk);
        } else {
            for (int kk = 0; kk < kmax; ++kk) GATH_STEP(kk);
        }
#undef GATH_STEP
    }

    // combine half-warps
#pragma unroll
    for (int i = 0; i < 8; ++i)
        acc[i] += __shfl_xor_sync(0xffffffffu, acc[i], 16);

    if (half == 0){
#pragma unroll
        for (int i = 0; i < 8; ++i) acc[i] = acc[i] > 0.0f ? acc[i] : 0.0f;
        uint4 o;
        __half2 p;
        p = __floats2half2_rn(acc[0], acc[1]); o.x = *reinterpret_cast<uint32_t*>(&p);
        p = __floats2half2_rn(acc[2], acc[3]); o.y = *reinterpret_cast<uint32_t*>(&p);
        p = __floats2half2_rn(acc[4], acc[5]); o.z = *reinterpret_cast<uint32_t*>(&p);
        p = __floats2half2_rn(acc[6], acc[7]); o.w = *reinterpret_cast<uint32_t*>(&p);
        reinterpret_cast<uint4*>(g_h2 + (size_t)cn*NH)[col16] = o;
    }
}

// ---------------- stage 5: C = H @ H^T, fp16 m16n8k16, upper-tri ------------
#define NTILES 8256          // 128*129/2
#define STGH (2*128*LDSH)    // halves per stage (A+B) = 10240 (20480 B)

__global__ void __launch_bounds__(256, 2) k_gemm(float* __restrict__ out){
    extern __shared__ __align__(16) char smc[];   // 3 stages fp16 / S_T fp32 overlay
    __half* smh = reinterpret_cast<__half*>(smc);
    float*  smf = reinterpret_cast<float*>(smc);

    int tid  = threadIdx.x;
    int lane = tid & 31;
    int wid  = tid >> 5;
    int m0w  = (wid >> 2) * 64;
    int n0w  = (wid & 3) * 32;
    int grp  = lane >> 2, qc = lane & 3;

    int tm = 0, rem = blockIdx.x;
    while (rem >= 128 - tm){ rem -= 128 - tm; tm++; }
    int tn = tm + rem;

    const __half* Ag = g_h2 + (size_t)tm * 128 * NH;
    const __half* Bg = g_h2 + (size_t)tn * 128 * NH;

    int lrow[2], lc4[2];
#pragma unroll
    for (int i = 0; i < 2; ++i){
        int idx = i*256 + tid;
        lrow[i] = idx >> 2; lc4[i] = idx & 3;
    }

#define PREFETCH(cidx, stage) do {                                              \
    __half* Asp = smh + (stage)*STGH;                                           \
    __half* Bsp = Asp + 128*LDSH;                                               \
    _Pragma("unroll")                                                           \
    for (int i = 0; i < 2; ++i){                                                \
        cp16(Asp + lrow[i]*LDSH + lc4[i]*8, Ag + lrow[i]*NH + (cidx)*KCH + lc4[i]*8); \
        cp16(Bsp + lrow[i]*LDSH + lc4[i]*8, Bg + lrow[i]*NH + (cidx)*KCH + lc4[i]*8); \
    }                                                                           \
    asm volatile("cp.async.commit_group;");                                     \
} while(0)

    float acc[4][4][4];
#pragma unroll
    for (int i = 0; i < 4; i++)
#pragma unroll
        for (int j = 0; j < 4; j++)
#pragma unroll
            for (int q = 0; q < 4; q++) acc[i][j][q] = 0.0f;

    PREFETCH(0, 0);
    PREFETCH(1, 1);

#pragma unroll
    for (int c = 0; c < 4; ++c){
        if (c < 3) asm volatile("cp.async.wait_group 1;");
        else       asm volatile("cp.async.wait_group 0;");
        __syncthreads();
        if (c + 2 < 4) PREFETCH(c + 2, (c + 2) % 3);

        __half* As = smh + (c % 3)*STGH;
        __half* Bs = As + 128*LDSH;
#pragma unroll
        for (int k16 = 0; k16 < KCH/16; ++k16){
            int kb = k16*16;
            uint32_t a[4][4], b[4][2];
#pragma unroll
            for (int mf = 0; mf < 4; ++mf){
                int r0 = m0w + mf*16 + grp;
                a[mf][0] = *reinterpret_cast<const uint32_t*>(As + r0*LDSH     + kb + 2*qc);
                a[mf][1] = *reinterpret_cast<const uint32_t*>(As + (r0+8)*LDSH + kb + 2*qc);
                a[mf][2] = *reinterpret_cast<const uint32_t*>(As + r0*LDSH     + kb + 2*qc + 8);
                a[mf][3] = *reinterpret_cast<const uint32_t*>(As + (r0+8)*LDSH + kb + 2*qc + 8);
            }
#pragma unroll
            for (int nf = 0; nf < 4; ++nf){
                int rn = n0w + nf*8 + grp;
                b[nf][0] = *reinterpret_cast<const uint32_t*>(Bs + rn*LDSH + kb + 2*qc);
                b[nf][1] = *reinterpret_cast<const uint32_t*>(Bs + rn*LDSH + kb + 2*qc + 8);
            }
#pragma unroll
            for (int mf = 0; mf < 4; ++mf)
#pragma unroll
                for (int nf = 0; nf < 4; ++nf)
                    mma_f16(acc[mf][nf], a[mf][0], a[mf][1], a[mf][2], a[mf][3],
                            b[nf][0], b[nf][1]);
        }
    }

    // direct (coalesced) streaming write of (tm, tn)
    float* outB = out + (size_t)(tm*128) * NN + (size_t)(tn*128);
#pragma unroll
    for (int mf = 0; mf < 4; ++mf)
#pragma unroll
        for (int nf = 0; nf < 4; ++nf){
            int r = m0w + mf*16 + grp;
            int c = n0w + nf*8 + 2*qc;
            __stcs(reinterpret_cast<float2*>(outB + (size_t)r*NN + c),
                   make_float2(acc[mf][nf][0], acc[mf][nf][1]));
            __stcs(reinterpret_cast<float2*>(outB + (size_t)(r+8)*NN + c),
                   make_float2(acc[mf][nf][2], acc[mf][nf][3]));
        }

    if (tm == tn) return;

    // mirrored (tn, tm): transposed fp32 staging, LDS.128 + streaming STG.128
    __syncthreads();
    float* S = smf;                  // S_T: 128 x TS floats = 67584 B
#pragma unroll
    for (int mf = 0; mf < 4; ++mf)
#pragma unroll
        for (int nf = 0; nf < 4; ++nf){
            int r = m0w + mf*16 + grp;
            int c = n0w + nf*8 + 2*qc;
            S[c*TS + r]         = acc[mf][nf][0];
            S[(c+1)*TS + r]     = acc[mf][nf][1];
            S[c*TS + r + 8]     = acc[mf][nf][2];
            S[(c+1)*TS + r + 8] = acc[mf][nf][3];
        }
    __syncthreads();

    float* outT = out + (size_t)(tn*128) * NN + (size_t)(tm*128);
    for (int j = wid; j < 128; j += 8){
        float4 v = *reinterpret_cast<const float4*>(S + j*TS + 4*lane);
        __stcs(reinterpret_cast<float4*>(outT + (size_t)j*NN + 4*lane), v);
    }
#undef PREFETCH
}

// ---------------- launcher: fork xw parallel to bucket build ----------------
extern "C" void kernel_launch(void* const* d_in, const int* in_sizes, int n_in,
                              void* d_out, int out_size){
    const float* x  = (const float*)d_in[0];
    const int*   ei = (const int*)d_in[1];
    const float* W  = (const float*)d_in[2];
    const float* b  = (const float*)d_in[3];
    float*       out = (float*)d_out;

    int smem_xw   = 2*128*LDSW*4;                 // 69632 B
    int smem_gemm = 128*TS*4;                     // 67584 B (> 3*STGH*2 = 61440 B)
    cudaFuncSetAttribute(k_xw,   cudaFuncAttributeMaxDynamicSharedMemorySize, smem_xw);
    cudaFuncSetAttribute(k_gemm, cudaFuncAttributeMaxDynamicSharedMemorySize, smem_gemm);

    // fork-join: k_xw (x,W only) runs concurrently with bucket build (ei only).
    cudaStream_t s1;
    cudaEvent_t e0, e1;
    cudaStreamCreateWithFlags(&s1, cudaStreamNonBlocking);
    cudaEventCreateWithFlags(&e0, cudaEventDisableTiming);
    cudaEventCreateWithFlags(&e1, cudaEventDisableTiming);

    cudaEventRecord(e0, 0);              // legacy (capture) stream
    cudaStreamWaitEvent(s1, e0, 0);
    k_xw<<<NN/128, 256, smem_xw, s1>>>(x, W);
    cudaEventRecord(e1, s1);

    k_init <<<NN/256, 256>>>();
    k_fill <<<(NE/4 + 255)/256, 256>>>(ei);

    cudaStreamWaitEvent(0, e1, 0);       // join: gather needs h and buckets
    k_gather <<<(NN*32)/256, 256>>>(b);
    k_gemm   <<<NTILES, 256, smem_gemm>>>(out);
}

// round 17
// speedup vs baseline: 1.5198x; 1.5198x over previous
#include <cuda_runtime.h>
#include <cuda_fp16.h>
#include <cstdint>

#define NN 16384
#define NH 128
#define NE (NN*32)
#define CAP 96     // bucket capacity: in-degree is Binom(524288,1/16384), 96 = 11 sigma

// ---------------- device scratch ----------------
__device__ int g_cnt[NN];                      // edges landed per target
__device__ __align__(16) float g_h[NN*NH];     // x @ W (fp32)
__device__ __align__(16) __half g_hh[NN*NH];   // fp16 copy of h (gather source)
__device__ __align__(16) __half g_h2[NN*NH];   // relu(gcn) in fp16
__device__ int g_csr[NN*CAP];                  // bucketed edge sources

#define KC 64
#define LDSW 68    // k_xw smem stride (floats)
#define KCH 32     // gemm k-chunk (halves)
#define LDSH 40    // gemm smem stride in halves: 80B rows (16B-aligned);
                   // frag word = (20*grp + qc)%32 bijective -> conflict-free
#define TS 132     // transposed staging stride (floats)

__device__ __forceinline__ float tf32r(float v){
    uint32_t t; asm("cvt.rna.tf32.f32 %0, %1;" : "=r"(t) : "f"(v));
    return __uint_as_float(t);
}
__device__ __forceinline__ void cp16(void* dst, const void* src){
    uint32_t d = (uint32_t)__cvta_generic_to_shared(dst);
    asm volatile("cp.async.cg.shared.global [%0], [%1], 16;" :: "r"(d), "l"(src));
}
__device__ __forceinline__ void mma_tf32(float* d,
        uint32_t a0, uint32_t a1, uint32_t a2, uint32_t a3,
        uint32_t b0, uint32_t b1){
    asm volatile(
        "mma.sync.aligned.m16n8k8.row.col.f32.tf32.tf32.f32 "
        "{%0,%1,%2,%3}, {%4,%5,%6,%7}, {%8,%9}, {%0,%1,%2,%3};"
        : "+f"(d[0]), "+f"(d[1]), "+f"(d[2]), "+f"(d[3])
        : "r"(a0), "r"(a1), "r"(a2), "r"(a3), "r"(b0), "r"(b1));
}
__device__ __forceinline__ void mma_f16(float* d,
        uint32_t a0, uint32_t a1, uint32_t a2, uint32_t a3,
        uint32_t b0, uint32_t b1){
    asm volatile(
        "mma.sync.aligned.m16n8k16.row.col.f32.f16.f16.f32 "
        "{%0,%1,%2,%3}, {%4,%5,%6,%7}, {%8,%9}, {%0,%1,%2,%3};"
        : "+f"(d[0]), "+f"(d[1]), "+f"(d[2]), "+f"(d[3])
        : "r"(a0), "r"(a1), "r"(a2), "r"(a3), "r"(b0), "r"(b1));
}

// ---------------- stage 1: zero bucket counters ----------------
__global__ void k_init(){
    int i = blockIdx.x * blockDim.x + threadIdx.x;
    if (i < NN) g_cnt[i] = 0;
}

// ---------------- stage 2: bucket fill, 4 edges/thread (int4) ---------------
__global__ void k_fill(const int* __restrict__ ei){
    int i = blockIdx.x * blockDim.x + threadIdx.x;
    if (i >= NE/4) return;
    int4 r = reinterpret_cast<const int4*>(ei)[i];
    int4 c = reinterpret_cast<const int4*>(ei + NE)[i];
    g_csr[c.x*CAP + atomicAdd(&g_cnt[c.x], 1)] = r.x;
    g_csr[c.y*CAP + atomicAdd(&g_cnt[c.y], 1)] = r.y;
    g_csr[c.z*CAP + atomicAdd(&g_cnt[c.z], 1)] = r.z;
    g_csr[c.w*CAP + atomicAdd(&g_cnt[c.w], 1)] = r.w;
}

// ---------------- stage 3: h = x @ W via tf32 mma (emits fp32 + fp16) -------
__global__ void __launch_bounds__(256, 2) k_xw(const float* __restrict__ x,
                                               const float* __restrict__ W){
    extern __shared__ float sm[];
    float* As = sm;
    float* Bs = sm + 128*LDSW;

    int tid  = threadIdx.x;
    int lane = tid & 31;
    int wid  = tid >> 5;
    int m0w  = (wid >> 2) * 64;
    int n0w  = (wid & 3) * 32;
    int row0 = blockIdx.x * 128;
    int grp  = lane >> 2, qc = lane & 3;

    float acc[4][4][4];
#pragma unroll
    for (int i = 0; i < 4; i++)
#pragma unroll
        for (int j = 0; j < 4; j++)
#pragma unroll
            for (int q = 0; q < 4; q++) acc[i][j][q] = 0.0f;

    for (int kc = 0; kc < 2; ++kc){
        if (kc) __syncthreads();
#pragma unroll
        for (int i = 0; i < 8; ++i){
            int idx = i*256 + tid;
            int r = idx >> 4, c4 = idx & 15;
            float4 v = *reinterpret_cast<const float4*>(x + (size_t)(row0 + r)*NH + kc*KC + c4*4);
            v.x = tf32r(v.x); v.y = tf32r(v.y); v.z = tf32r(v.z); v.w = tf32r(v.w);
            *reinterpret_cast<float4*>(As + r*LDSW + c4*4) = v;
        }
#pragma unroll
        for (int i = 0; i < 8; ++i){
            int idx = i*256 + tid;
            int n = idx & 127, kk4 = idx >> 7;
            float4 v;
            v.x = tf32r(W[(size_t)(kc*KC + kk4*4 + 0)*NH + n]);
            v.y = tf32r(W[(size_t)(kc*KC + kk4*4 + 1)*NH + n]);
            v.z = tf32r(W[(size_t)(kc*KC + kk4*4 + 2)*NH + n]);
            v.w = tf32r(W[(size_t)(kc*KC + kk4*4 + 3)*NH + n]);
            *reinterpret_cast<float4*>(Bs + n*LDSW + kk4*4) = v;
        }
        __syncthreads();

#pragma unroll
        for (int k8 = 0; k8 < KC/8; ++k8){
            int kb = k8*8;
            uint32_t a[4][4], b[4][2];
#pragma unroll
            for (int mf = 0; mf < 4; ++mf){
                int r0 = m0w + mf*16 + grp;
                a[mf][0] = __float_as_uint(As[r0*LDSW     + kb + qc]);
                a[mf][1] = __float_as_uint(As[(r0+8)*LDSW + kb + qc]);
                a[mf][2] = __float_as_uint(As[r0*LDSW     + kb + qc + 4]);
                a[mf][3] = __float_as_uint(As[(r0+8)*LDSW + kb + qc + 4]);
            }
#pragma unroll
            for (int nf = 0; nf < 4; ++nf){
                int rn = n0w + nf*8 + grp;
                b[nf][0] = __float_as_uint(Bs[rn*LDSW + kb + qc]);
                b[nf][1] = __float_as_uint(Bs[rn*LDSW + kb + qc + 4]);
            }
#pragma unroll
            for (int mf = 0; mf < 4; ++mf)
#pragma unroll
                for (int nf = 0; nf < 4; ++nf)
                    mma_tf32(acc[mf][nf], a[mf][0], a[mf][1], a[mf][2], a[mf][3],
                             b[nf][0], b[nf][1]);
        }
    }

#pragma unroll
    for (int mf = 0; mf < 4; ++mf)
#pragma unroll
        for (int nf = 0; nf < 4; ++nf){
            int r = m0w + mf*16 + grp;
            int c = n0w + nf*8 + 2*qc;
            *reinterpret_cast<float2*>(g_h + (size_t)(row0 + r)*NH + c) =
                make_float2(acc[mf][nf][0], acc[mf][nf][1]);
            *reinterpret_cast<float2*>(g_h + (size_t)(row0 + r + 8)*NH + c) =
                make_float2(acc[mf][nf][2], acc[mf][nf][3]);
            reinterpret_cast<__half2*>(g_hh + (size_t)(row0 + r)*NH)[c>>1] =
                __floats2half2_rn(acc[mf][nf][0], acc[mf][nf][1]);
            reinterpret_cast<__half2*>(g_hh + (size_t)(row0 + r + 8)*NH)[c>>1] =
                __floats2half2_rn(acc[mf][nf][2], acc[mf][nf][3]);
        }
}

// ---------------- stage 4: fused gather (fp16 src) + self + bias + relu -----
__global__ void k_gather(const float* __restrict__ bias){
    int warp = (blockIdx.x * blockDim.x + threadIdx.x) >> 5;
    if (warp >= NN) return;
    int lane = threadIdx.x & 31;
    int cn = warp;

    int   cntc = g_cnt[cn];
    float degc = (float)(cntc + 1);          // + self-loop
    float dic  = rsqrtf(degc);
    int beg = cn*CAP, end = cn*CAP + cntc;

    const float4* hc = reinterpret_cast<const float4*>(g_h + (size_t)cn*NH) + lane;
    float4 acc = *hc;
    float inv = 1.0f / degc;
    acc.x *= inv; acc.y *= inv; acc.z *= inv; acc.w *= inv;

    for (int j = beg; j < end; j += 32){
        int me = j + lane;
        int src = 0; float wsrc = 0.0f;
        if (me < end){
            src  = g_csr[me];
            wsrc = dic * rsqrtf((float)(g_cnt[src] + 1));
        }
        int cnt = min(32, end - j);
        if (cnt == 32){
#pragma unroll
            for (int k = 0; k < 32; ++k){
                int   r = __shfl_sync(0xffffffffu, src,  k);
                float w = __shfl_sync(0xffffffffu, wsrc, k);
                uint2 hv = reinterpret_cast<const uint2*>(g_hh + (size_t)r*NH)[lane];
                float2 f01 = __half22float2(*reinterpret_cast<__half2*>(&hv.x));
                float2 f23 = __half22float2(*reinterpret_cast<__half2*>(&hv.y));
                acc.x += w*f01.x; acc.y += w*f01.y; acc.z += w*f23.x; acc.w += w*f23.y;
            }
        } else {
            for (int k = 0; k < cnt; ++k){
                int   r = __shfl_sync(0xffffffffu, src,  k);
                float w = __shfl_sync(0xffffffffu, wsrc, k);
                uint2 hv = reinterpret_cast<const uint2*>(g_hh + (size_t)r*NH)[lane];
                float2 f01 = __half22float2(*reinterpret_cast<__half2*>(&hv.x));
                float2 f23 = __half22float2(*reinterpret_cast<__half2*>(&hv.y));
                acc.x += w*f01.x; acc.y += w*f01.y; acc.z += w*f23.x; acc.w += w*f23.y;
            }
        }
    }

    float4 bv = *(reinterpret_cast<const float4*>(bias) + lane);
    acc.x += bv.x; acc.y += bv.y; acc.z += bv.z; acc.w += bv.w;
    acc.x = acc.x > 0.0f ? acc.x : 0.0f;
    acc.y = acc.y > 0.0f ? acc.y : 0.0f;
    acc.z = acc.z > 0.0f ? acc.z : 0.0f;
    acc.w = acc.w > 0.0f ? acc.w : 0.0f;
    __half2 p0 = __floats2half2_rn(acc.x, acc.y);
    __half2 p1 = __floats2half2_rn(acc.z, acc.w);
    reinterpret_cast<__half2*>(g_h2 + (size_t)cn*NH)[2*lane]     = p0;
    reinterpret_cast<__half2*>(g_h2 + (size_t)cn*NH)[2*lane + 1] = p1;
}

// ---------------- stage 5: C = H @ H^T, fp16 m16n8k16, upper-tri ------------
#define NTILES 8256          // 128*129/2
#define STGH (2*128*LDSH)    // halves per stage (A+B) = 10240 (20480 B)

__global__ void __launch_bounds__(256, 2) k_gemm(float* __restrict__ out){
    extern __shared__ __align__(16) char smc[];   // 3 stages fp16 / S_T fp32 overlay
    __half* smh = reinterpret_cast<__half*>(smc);
    float*  smf = reinterpret_cast<float*>(smc);

    int tid  = threadIdx.x;
    int lane = tid & 31;
    int wid  = tid >> 5;
    int m0w  = (wid >> 2) * 64;
    int n0w  = (wid & 3) * 32;
    int grp  = lane >> 2, qc = lane & 3;

    int tm = 0, rem = blockIdx.x;
    while (rem >= 128 - tm){ rem -= 128 - tm; tm++; }
    int tn = tm + rem;

    const __half* Ag = g_h2 + (size_t)tm * 128 * NH;
    const __half* Bg = g_h2 + (size_t)tn * 128 * NH;

    int lrow[2], lc4[2];
#pragma unroll
    for (int i = 0; i < 2; ++i){
        int idx = i*256 + tid;
        lrow[i] = idx >> 2; lc4[i] = idx & 3;
    }

#define PREFETCH(cidx, stage) do {                                              \
    __half* Asp = smh + (stage)*STGH;                                           \
    __half* Bsp = Asp + 128*LDSH;                                               \
    _Pragma("unroll")                                                           \
    for (int i = 0; i < 2; ++i){                                                \
        cp16(Asp + lrow[i]*LDSH + lc4[i]*8, Ag + lrow[i]*NH + (cidx)*KCH + lc4[i]*8); \
        cp16(Bsp + lrow[i]*LDSH + lc4[i]*8, Bg + lrow[i]*NH + (cidx)*KCH + lc4[i]*8); \
    }                                                                           \
    asm volatile("cp.async.commit_group;");                                     \
} while(0)

    float acc[4][4][4];
#pragma unroll
    for (int i = 0; i < 4; i++)
#pragma unroll
        for (int j = 0; j < 4; j++)
#pragma unroll
            for (int q = 0; q < 4; q++) acc[i][j][q] = 0.0f;

    PREFETCH(0, 0);
    PREFETCH(1, 1);

#pragma unroll
    for (int c = 0; c < 4; ++c){
        if (c < 3) asm volatile("cp.async.wait_group 1;");
        else       asm volatile("cp.async.wait_group 0;");
        __syncthreads();
        if (c + 2 < 4) PREFETCH(c + 2, (c + 2) % 3);

        __half* As = smh + (c % 3)*STGH;
        __half* Bs = As + 128*LDSH;
#pragma unroll
        for (int k16 = 0; k16 < KCH/16; ++k16){
            int kb = k16*16;
            uint32_t a[4][4], b[4][2];
#pragma unroll
            for (int mf = 0; mf < 4; ++mf){
                int r0 = m0w + mf*16 + grp;
                a[mf][0] = *reinterpret_cast<const uint32_t*>(As + r0*LDSH     + kb + 2*qc);
                a[mf][1] = *reinterpret_cast<const uint32_t*>(As + (r0+8)*LDSH + kb + 2*qc);
                a[mf][2] = *reinterpret_cast<const uint32_t*>(As + r0*LDSH     + kb + 2*qc + 8);
                a[mf][3] = *reinterpret_cast<const uint32_t*>(As + (r0+8)*LDSH + kb + 2*qc + 8);
            }
#pragma unroll
            for (int nf = 0; nf < 4; ++nf){
                int rn = n0w + nf*8 + grp;
                b[nf][0] = *reinterpret_cast<const uint32_t*>(Bs + rn*LDSH + kb + 2*qc);
                b[nf][1] = *reinterpret_cast<const uint32_t*>(Bs + rn*LDSH + kb + 2*qc + 8);
            }
#pragma unroll
            for (int mf = 0; mf < 4; ++mf)
#pragma unroll
                for (int nf = 0; nf < 4; ++nf)
                    mma_f16(acc[mf][nf], a[mf][0], a[mf][1], a[mf][2], a[mf][3],
                            b[nf][0], b[nf][1]);
        }
    }

    // direct (coalesced) streaming write of (tm, tn)
    float* outB = out + (size_t)(tm*128) * NN + (size_t)(tn*128);
#pragma unroll
    for (int mf = 0; mf < 4; ++mf)
#pragma unroll
        for (int nf = 0; nf < 4; ++nf){
            int r = m0w + mf*16 + grp;
            int c = n0w + nf*8 + 2*qc;
            __stcs(reinterpret_cast<float2*>(outB + (size_t)r*NN + c),
                   make_float2(acc[mf][nf][0], acc[mf][nf][1]));
            __stcs(reinterpret_cast<float2*>(outB + (size_t)(r+8)*NN + c),
                   make_float2(acc[mf][nf][2], acc[mf][nf][3]));
        }

    if (tm == tn) return;

    // mirrored (tn, tm): transposed fp32 staging, LDS.128 + streaming STG.128
    __syncthreads();
    float* S = smf;                  // S_T: 128 x TS floats = 67584 B
#pragma unroll
    for (int mf = 0; mf < 4; ++mf)
#pragma unroll
        for (int nf = 0; nf < 4; ++nf){
            int r = m0w + mf*16 + grp;
            int c = n0w + nf*8 + 2*qc;
            S[c*TS + r]         = acc[mf][nf][0];
            S[(c+1)*TS + r]     = acc[mf][nf][1];
            S[c*TS + r + 8]     = acc[mf][nf][2];
            S[(c+1)*TS + r + 8] = acc[mf][nf][3];
        }
    __syncthreads();

    float* outT = out + (size_t)(tn*128) * NN + (size_t)(tm*128);
    for (int j = wid; j < 128; j += 8){
        float4 v = *reinterpret_cast<const float4*>(S + j*TS + 4*lane);
        __stcs(reinterpret_cast<float4*>(outT + (size_t)j*NN + 4*lane), v);
    }
#undef PREFETCH
}

// ---------------- launcher: fork xw parallel to bucket build ----------------
extern "C" void kernel_launch(void* const* d_in, const int* in_sizes, int n_in,
                              void* d_out, int out_size){
    const float* x  = (const float*)d_in[0];
    const int*   ei = (const int*)d_in[1];
    const float* W  = (const float*)d_in[2];
    const float* b  = (const float*)d_in[3];
    float*       out = (float*)d_out;

    int smem_xw   = 2*128*LDSW*4;                 // 69632 B
    int smem_gemm = 128*TS*4;                     // 67584 B (> 3*STGH*2 = 61440 B)
    cudaFuncSetAttribute(k_xw,   cudaFuncAttributeMaxDynamicSharedMemorySize, smem_xw);
    cudaFuncSetAttribute(k_gemm, cudaFuncAttributeMaxDynamicSharedMemorySize, smem_gemm);

    // fork-join: k_xw (x,W only) runs concurrently with bucket build (ei only).
    cudaStream_t s1;
    cudaEvent_t e0, e1;
    cudaStreamCreateWithFlags(&s1, cudaStreamNonBlocking);
    cudaEventCreateWithFlags(&e0, cudaEventDisableTiming);
    cudaEventCreateWithFlags(&e1, cudaEventDisableTiming);

    cudaEventRecord(e0, 0);              // legacy (capture) stream
    cudaStreamWaitEvent(s1, e0, 0);
    k_xw<<<NN/128, 256, smem_xw, s1>>>(x, W);
    cudaEventRecord(e1, s1);

    k_init <<<NN/256, 256>>>();
    k_fill <<<(NE/4 + 255)/256, 256>>>(ei);

    cudaStreamWaitEvent(0, e1, 0);       // join: gather needs h and buckets
    k_gather <<<(NN*32)/256, 256>>>(b);
    k_gemm   <<<NTILES, 256, smem_gemm>>>(out);
}